// round 4
// baseline (speedup 1.0000x reference)
#include <cuda_runtime.h>
#include <cstdint>

#define B_MAX 65536
#define CHUNK_K 8
#define NCHUNK_PER_LAYER 8   // 64 / CHUNK_K
#define NCHUNK_TOTAL 32      // 4 layers * NCHUNK_PER_LAYER

// ---------------- device scratch (no allocs allowed) ----------------
__device__ float g_whh [4 * 64 * 64 * 4];   // [l][k][j][gate]
__device__ float g_wih [3 * 64 * 64 * 4];   // [l-1][k][j][gate]
__device__ float g_wih0[3 * 64 * 4];        // [kx][j][gate]
__device__ float g_bias[4 * 64 * 4];        // [l][j][gate]  (b_ih + b_hh)
__device__ float g_init[(size_t)B_MAX * 128]; // [b][128] = (h0 | c0)

typedef unsigned long long ull;

__device__ __forceinline__ ull splat2(float x) {
    ull r; asm("mov.b64 %0, {%1, %1};" : "=l"(r) : "f"(x)); return r;
}
__device__ __forceinline__ ull fma2(ull a, ull b, ull c) {
    ull d; asm("fma.rn.f32x2 %0, %1, %2, %3;" : "=l"(d) : "l"(a), "l"(b), "l"(c)); return d;
}
__device__ __forceinline__ float2 u2f(ull a) {
    float2 f; asm("mov.b64 {%0, %1}, %2;" : "=f"(f.x), "=f"(f.y) : "l"(a)); return f;
}
__device__ __forceinline__ float sigm(float x) {
    return __fdividef(1.f, 1.f + __expf(-x));
}
__device__ __forceinline__ float tanh_(float x) {
    float ax = fabsf(x);
    float e = __expf(-2.f * ax);
    float r = __fdividef(1.f - e, 1.f + e);
    return copysignf(r, x);
}
__device__ __forceinline__ void cp16(uint32_t dst, const void* src) {
    asm volatile("cp.async.cg.shared.global [%0], [%1], 16;" :: "r"(dst), "l"(src));
}

// ---------------- prologue 1: weight repack ----------------
__global__ void repack_k(const float* __restrict__ W_ih0,
                         const float* __restrict__ W_ih_rest,
                         const float* __restrict__ W_hh,
                         const float* __restrict__ b_ih,
                         const float* __restrict__ b_hh) {
    int idx = blockIdx.x * blockDim.x + threadIdx.x;
    const int N_WHH  = 4 * 256 * 64;
    const int N_WIH  = 3 * 256 * 64;
    const int N_WIH0 = 256 * 3;
    const int N_BIAS = 4 * 256;
    if (idx < N_WHH) {
        int k = idx & 63, row = (idx >> 6) & 255, l = idx >> 14;
        int g = row >> 6, j = row & 63;
        g_whh[(((l * 64 + k) * 64) + j) * 4 + g] = W_hh[idx];
        return;
    }
    idx -= N_WHH;
    if (idx < N_WIH) {
        int k = idx & 63, row = (idx >> 6) & 255, lm1 = idx >> 14;
        int g = row >> 6, j = row & 63;
        g_wih[(((lm1 * 64 + k) * 64) + j) * 4 + g] = W_ih_rest[idx];
        return;
    }
    idx -= N_WIH;
    if (idx < N_WIH0) {
        int row = idx / 3, kx = idx % 3;
        int g = row >> 6, j = row & 63;
        g_wih0[(kx * 64 + j) * 4 + g] = W_ih0[idx];
        return;
    }
    idx -= N_WIH0;
    if (idx < N_BIAS) {
        int l = idx >> 8, row = idx & 255;
        int g = row >> 6, j = row & 63;
        g_bias[(l * 64 + j) * 4 + g] = b_ih[l * 256 + row] + b_hh[l * 256 + row];
    }
}

// ---------------- prologue 2: decoder_fc -> (h0|c0) ----------------
__global__ void embed_k(const float* __restrict__ conds,
                        const float* __restrict__ W1, const float* __restrict__ b1,
                        const float* __restrict__ W2, const float* __restrict__ b2) {
    int b = blockIdx.x;
    __shared__ float hid[64];
    __shared__ float cnd[8];
    int t = threadIdx.x;  // 128 threads
    if (t < 8) cnd[t] = conds[b * 8 + t];
    __syncthreads();
    if (t < 64) {
        float a = b1[t];
        #pragma unroll
        for (int k = 0; k < 8; k++) a += cnd[k] * W1[t * 8 + k];
        hid[t] = fmaxf(a, 0.f);
    }
    __syncthreads();
    float a = b2[t];
    #pragma unroll
    for (int k = 0; k < 64; k++) a += hid[k] * W2[t * 64 + k];
    g_init[(size_t)b * 128 + t] = a;
}

// ---------------- main kernel ----------------
struct Smem {
    float4 wbuf[2][2][CHUNK_K][64];  // [buf][mat(0=whh,1=wih)][kk][j] : 32 KB
    float  h[4][64][32];             // 32 KB
    float  x[3][32];
};

// prefetch global-chunk gc (0..31) into wbuf[gc&1]; commits one cp.async group
__device__ __forceinline__ void prefetch_chunk(Smem* sm, int gc, int tid) {
    int l = gc >> 3, c = gc & 7, pb = gc & 1;
    const float4* srcA = ((const float4*)g_whh) + (l * 64 + c * CHUNK_K) * 64;
    float4* dstA = &sm->wbuf[pb][0][0][0];
    #pragma unroll
    for (int i = 0; i < (CHUNK_K * 64) / 256; i++) {  // 2 float4 per thread
        int f = tid + i * 256;
        cp16((uint32_t)__cvta_generic_to_shared(dstA + f), srcA + f);
    }
    if (l > 0) {
        const float4* srcB = ((const float4*)g_wih) + ((l - 1) * 64 + c * CHUNK_K) * 64;
        float4* dstB = &sm->wbuf[pb][1][0][0];
        #pragma unroll
        for (int i = 0; i < (CHUNK_K * 64) / 256; i++) {
            int f = tid + i * 256;
            cp16((uint32_t)__cvta_generic_to_shared(dstB + f), srcB + f);
        }
    }
    asm volatile("cp.async.commit_group;" ::: "memory");
}

#define FMA2_BCAST(A, W, Xa, Xb)            \
    A[0] = fma2(W, Xa.x, A[0]);             \
    A[1] = fma2(W, Xa.y, A[1]);             \
    A[2] = fma2(W, Xb.x, A[2]);             \
    A[3] = fma2(W, Xb.y, A[3]);

__global__ __launch_bounds__(256, 2)
void lstm_main(const float* __restrict__ Wo, const float* __restrict__ bo,
               float* __restrict__ out, int T) {
    extern __shared__ __align__(16) unsigned char smem_raw[];
    Smem* sm = reinterpret_cast<Smem*>(smem_raw);

    const int tid = threadIdx.x;
    const int j = tid & 63;
    const int y = tid >> 6;
    const int bb0 = blockIdx.x * 32;
    const int bthr = bb0 + y * 8;

    float c0[8], c1[8], c2[8], c3[8];

    // init h/c from embed, x from [0.5, 0.5, 0]
    #pragma unroll
    for (int i = 0; i < 8; i++) {
        const float* gi = g_init + (size_t)(bthr + i) * 128;
        float hv = gi[j];
        float cv = gi[64 + j];
        int pos = ((y * 8 + i) + 8 * (j & 3)) & 31;
        sm->h[0][j][pos] = hv; sm->h[1][j][pos] = hv;
        sm->h[2][j][pos] = hv; sm->h[3][j][pos] = hv;
        c0[i] = cv; c1[i] = cv; c2[i] = cv; c3[i] = cv;
    }
    if (tid < 96) {
        int kx = tid >> 5, b = tid & 31;
        sm->x[kx][b] = (kx == 2) ? 0.f : 0.5f;
    }

    // prime the weight pipeline (chunks 0, 1)
    prefetch_chunk(sm, 0, tid);
    prefetch_chunk(sm, 1, tid);
    __syncthreads();

    const float4* BIA = ((const float4*)g_bias) + j;  // + l*64
    const float4* WI0 = ((const float4*)g_wih0) + j;  // + kx*64
    const int base_rb = y * 8;

    for (int t = 0; t < T; t++) {
        #pragma unroll
        for (int l = 0; l < 4; l++) {
            float4 bv = BIA[l * 64];
            ull a0[4], a1[4], a2[4], a3[4];
            {
                ull s0 = splat2(bv.x), s1 = splat2(bv.y), s2 = splat2(bv.z), s3 = splat2(bv.w);
                #pragma unroll
                for (int p = 0; p < 4; p++) { a0[p] = s0; a1[p] = s1; a2[p] = s2; a3[p] = s3; }
            }
            if (l == 0) {
                // input part: x (3 features)  (x_s valid: written before last barrier)
                #pragma unroll
                for (int kx = 0; kx < 3; kx++) {
                    float4 wi = WI0[kx * 64];
                    const ulonglong2* xp = (const ulonglong2*)&sm->x[kx][base_rb];
                    ulonglong2 xa = xp[0], xb = xp[1];
                    ull w;
                    w = splat2(wi.x); FMA2_BCAST(a0, w, xa, xb);
                    w = splat2(wi.y); FMA2_BCAST(a1, w, xa, xb);
                    w = splat2(wi.z); FMA2_BCAST(a2, w, xa, xb);
                    w = splat2(wi.w); FMA2_BCAST(a3, w, xa, xb);
                }
            }

            for (int c = 0; c < NCHUNK_PER_LAYER; c++) {
                const int gc = l * NCHUNK_PER_LAYER + c;
                asm volatile("cp.async.wait_group 1;" ::: "memory");
                __syncthreads();   // chunk gc staged & visible; h writes of prev layer visible

                const int pb = gc & 1;
                const float4* WH = &sm->wbuf[pb][0][0][j];
                const float4* WI = &sm->wbuf[pb][1][0][j];
                const int k0 = c * CHUNK_K;

                if (l == 0) {
                    #pragma unroll 4
                    for (int kk = 0; kk < CHUNK_K; kk++) {
                        float4 wh = WH[kk * 64];
                        int rb = (base_rb + 8 * (kk & 3)) & 31;
                        const ulonglong2* hp = (const ulonglong2*)&sm->h[0][k0 + kk][rb];
                        ulonglong2 ha = hp[0], hb = hp[1];
                        ull w;
                        w = splat2(wh.x); FMA2_BCAST(a0, w, ha, hb);
                        w = splat2(wh.y); FMA2_BCAST(a1, w, ha, hb);
                        w = splat2(wh.z); FMA2_BCAST(a2, w, ha, hb);
                        w = splat2(wh.w); FMA2_BCAST(a3, w, ha, hb);
                    }
                } else {
                    #pragma unroll 4
                    for (int kk = 0; kk < CHUNK_K; kk++) {
                        float4 wh = WH[kk * 64];
                        float4 wi = WI[kk * 64];
                        int rb = (base_rb + 8 * (kk & 3)) & 31;
                        const ulonglong2* hp = (const ulonglong2*)&sm->h[l][k0 + kk][rb];
                        const ulonglong2* ip = (const ulonglong2*)&sm->h[l - 1][k0 + kk][rb];
                        ulonglong2 ha = hp[0], hb = hp[1];
                        ulonglong2 xa = ip[0], xb = ip[1];
                        ull w;
                        w = splat2(wh.x); FMA2_BCAST(a0, w, ha, hb);
                        w = splat2(wh.y); FMA2_BCAST(a1, w, ha, hb);
                        w = splat2(wh.z); FMA2_BCAST(a2, w, ha, hb);
                        w = splat2(wh.w); FMA2_BCAST(a3, w, ha, hb);
                        w = splat2(wi.x); FMA2_BCAST(a0, w, xa, xb);
                        w = splat2(wi.y); FMA2_BCAST(a1, w, xa, xb);
                        w = splat2(wi.z); FMA2_BCAST(a2, w, xa, xb);
                        w = splat2(wi.w); FMA2_BCAST(a3, w, xa, xb);
                    }
                }
                __syncthreads();   // all reads of wbuf[pb] (and h for this chunk) done
                prefetch_chunk(sm, (gc + 2) & (NCHUNK_TOTAL - 1), tid);
            }

            // gate nonlinearities + h/c update
            const int wbase = (base_rb + 8 * (j & 3)) & 31;
            #define DO_UPDATE(C)                                                        \
            {                                                                           \
                _Pragma("unroll")                                                       \
                for (int p = 0; p < 4; p++) {                                           \
                    float2 iv = u2f(a0[p]), fv = u2f(a1[p]);                            \
                    float2 gv = u2f(a2[p]), ov = u2f(a3[p]);                            \
                    float cn0 = sigm(fv.x) * C[2 * p]     + sigm(iv.x) * tanh_(gv.x);   \
                    float cn1 = sigm(fv.y) * C[2 * p + 1] + sigm(iv.y) * tanh_(gv.y);   \
                    C[2 * p] = cn0; C[2 * p + 1] = cn1;                                 \
                    sm->h[l][j][wbase + 2 * p]     = sigm(ov.x) * tanh_(cn0);           \
                    sm->h[l][j][wbase + 2 * p + 1] = sigm(ov.y) * tanh_(cn1);           \
                }                                                                       \
            }
            if (l == 0)      DO_UPDATE(c0)
            else if (l == 1) DO_UPDATE(c1)
            else if (l == 2) DO_UPDATE(c2)
            else             DO_UPDATE(c3)
            #undef DO_UPDATE
        }
        __syncthreads();   // h[3] update visible to pred readers

        // pred = h[3] @ Wo.T + bo  (96 threads: (jo, b))
        if (tid < 96) {
            int b = tid & 31, jo = tid >> 5;
            float acc = __ldg(&bo[jo]);
            #pragma unroll 4
            for (int k = 0; k < 64; k++) {
                acc += __ldg(&Wo[jo * 64 + k]) * sm->h[3][k][(b + 8 * (k & 3)) & 31];
            }
            sm->x[jo][b] = acc;
            out[(size_t)(bb0 + b) * (3 * T) + t * 3 + jo] = acc;
        }
        __syncthreads();  // x ready for next step's layer 0
    }
}

// ---------------- entry ----------------
extern "C" void kernel_launch(void* const* d_in, const int* in_sizes, int n_in,
                              void* d_out, int out_size) {
    const float* conds     = (const float*)d_in[0];
    const float* W1        = (const float*)d_in[1];
    const float* b1        = (const float*)d_in[2];
    const float* W2        = (const float*)d_in[3];
    const float* b2        = (const float*)d_in[4];
    const float* W_ih0     = (const float*)d_in[5];
    const float* W_ih_rest = (const float*)d_in[6];
    const float* W_hh      = (const float*)d_in[7];
    const float* b_ih      = (const float*)d_in[8];
    const float* b_hh      = (const float*)d_in[9];
    const float* Wo        = (const float*)d_in[10];
    const float* bo        = (const float*)d_in[11];

    int B = in_sizes[0] / 8;
    if (B > B_MAX) B = B_MAX;
    int T = out_size / (B * 3);

    // dynamic smem (66 KB/CTA > 48 KB static limit; 2 CTAs/SM = 132 KB <= 228 KB)
    cudaFuncSetAttribute(lstm_main, cudaFuncAttributeMaxDynamicSharedMemorySize,
                         (int)sizeof(Smem));

    const int total_repack = 4 * 256 * 64 + 3 * 256 * 64 + 256 * 3 + 4 * 256;
    repack_k<<<(total_repack + 255) / 256, 256>>>(W_ih0, W_ih_rest, W_hh, b_ih, b_hh);
    embed_k<<<B, 128>>>(conds, W1, b1, W2, b2);
    lstm_main<<<B / 32, 256, sizeof(Smem)>>>(Wo, bo, (float*)d_out, T);
}

// round 5
// speedup vs baseline: 1.0004x; 1.0004x over previous
#include <cuda_runtime.h>
#include <cstdint>

#define B_MAX 65536
#define CHUNK_K 8
#define NCHUNK_PER_LAYER 8   // 64 / CHUNK_K
#define NCHUNK_TOTAL 32      // 4 layers * NCHUNK_PER_LAYER

// ---------------- device scratch (no allocs allowed) ----------------
__device__ float g_whh [4 * 64 * 64 * 4];   // [l][k][j][gate]
__device__ float g_wih [3 * 64 * 64 * 4];   // [l-1][k][j][gate]
__device__ float g_wih0[3 * 64 * 4];        // [kx][j][gate]
__device__ float g_bias[4 * 64 * 4];        // [l][j][gate]  (b_ih + b_hh)
__device__ float g_init[(size_t)B_MAX * 128]; // [b][128] = (h0 | c0)

typedef unsigned long long ull;

__device__ __forceinline__ ull splat2(float x) {
    ull r; asm("mov.b64 %0, {%1, %1};" : "=l"(r) : "f"(x)); return r;
}
__device__ __forceinline__ ull fma2(ull a, ull b, ull c) {
    ull d; asm("fma.rn.f32x2 %0, %1, %2, %3;" : "=l"(d) : "l"(a), "l"(b), "l"(c)); return d;
}
__device__ __forceinline__ float2 u2f(ull a) {
    float2 f; asm("mov.b64 {%0, %1}, %2;" : "=f"(f.x), "=f"(f.y) : "l"(a)); return f;
}
__device__ __forceinline__ float sigm(float x) {
    return __fdividef(1.f, 1.f + __expf(-x));
}
__device__ __forceinline__ float tanh_(float x) {
    float ax = fabsf(x);
    float e = __expf(-2.f * ax);
    float r = __fdividef(1.f - e, 1.f + e);
    return copysignf(r, x);
}
__device__ __forceinline__ void cp16(uint32_t dst, const void* src) {
    asm volatile("cp.async.cg.shared.global [%0], [%1], 16;" :: "r"(dst), "l"(src));
}

// ---------------- prologue 1: weight repack ----------------
__global__ void repack_k(const float* __restrict__ W_ih0,
                         const float* __restrict__ W_ih_rest,
                         const float* __restrict__ W_hh,
                         const float* __restrict__ b_ih,
                         const float* __restrict__ b_hh) {
    int idx = blockIdx.x * blockDim.x + threadIdx.x;
    const int N_WHH  = 4 * 256 * 64;
    const int N_WIH  = 3 * 256 * 64;
    const int N_WIH0 = 256 * 3;
    const int N_BIAS = 4 * 256;
    if (idx < N_WHH) {
        int k = idx & 63, row = (idx >> 6) & 255, l = idx >> 14;
        int g = row >> 6, j = row & 63;
        g_whh[(((l * 64 + k) * 64) + j) * 4 + g] = W_hh[idx];
        return;
    }
    idx -= N_WHH;
    if (idx < N_WIH) {
        int k = idx & 63, row = (idx >> 6) & 255, lm1 = idx >> 14;
        int g = row >> 6, j = row & 63;
        g_wih[(((lm1 * 64 + k) * 64) + j) * 4 + g] = W_ih_rest[idx];
        return;
    }
    idx -= N_WIH;
    if (idx < N_WIH0) {
        int row = idx / 3, kx = idx % 3;
        int g = row >> 6, j = row & 63;
        g_wih0[(kx * 64 + j) * 4 + g] = W_ih0[idx];
        return;
    }
    idx -= N_WIH0;
    if (idx < N_BIAS) {
        int l = idx >> 8, row = idx & 255;
        int g = row >> 6, j = row & 63;
        g_bias[(l * 64 + j) * 4 + g] = b_ih[l * 256 + row] + b_hh[l * 256 + row];
    }
}

// ---------------- prologue 2: decoder_fc -> (h0|c0) ----------------
__global__ void embed_k(const float* __restrict__ conds,
                        const float* __restrict__ W1, const float* __restrict__ b1,
                        const float* __restrict__ W2, const float* __restrict__ b2) {
    int b = blockIdx.x;
    __shared__ float hid[64];
    __shared__ float cnd[8];
    int t = threadIdx.x;  // 128 threads
    if (t < 8) cnd[t] = conds[b * 8 + t];
    __syncthreads();
    if (t < 64) {
        float a = b1[t];
        #pragma unroll
        for (int k = 0; k < 8; k++) a += cnd[k] * W1[t * 8 + k];
        hid[t] = fmaxf(a, 0.f);
    }
    __syncthreads();
    float a = b2[t];
    #pragma unroll
    for (int k = 0; k < 64; k++) a += hid[k] * W2[t * 64 + k];
    g_init[(size_t)b * 128 + t] = a;
}

// ---------------- main kernel ----------------
struct Smem {
    float4 wbuf[2][2][CHUNK_K][64];  // [buf][mat(0=whh,1=wih)][kk][j] : 32 KB
    float  h[4][64][32];             // 32 KB
    float  x[3][32];
};

// prefetch global-chunk gc (0..31) into wbuf[gc&1]; commits one cp.async group
__device__ __forceinline__ void prefetch_chunk(Smem* sm, int gc, int tid) {
    int l = gc >> 3, c = gc & 7, pb = gc & 1;
    const float4* srcA = ((const float4*)g_whh) + (l * 64 + c * CHUNK_K) * 64;
    float4* dstA = &sm->wbuf[pb][0][0][0];
    #pragma unroll
    for (int i = 0; i < (CHUNK_K * 64) / 256; i++) {  // 2 float4 per thread
        int f = tid + i * 256;
        cp16((uint32_t)__cvta_generic_to_shared(dstA + f), srcA + f);
    }
    if (l > 0) {
        const float4* srcB = ((const float4*)g_wih) + ((l - 1) * 64 + c * CHUNK_K) * 64;
        float4* dstB = &sm->wbuf[pb][1][0][0];
        #pragma unroll
        for (int i = 0; i < (CHUNK_K * 64) / 256; i++) {
            int f = tid + i * 256;
            cp16((uint32_t)__cvta_generic_to_shared(dstB + f), srcB + f);
        }
    }
    asm volatile("cp.async.commit_group;" ::: "memory");
}

#define FMA2_BCAST(A, W, Xa, Xb)            \
    A[0] = fma2(W, Xa.x, A[0]);             \
    A[1] = fma2(W, Xa.y, A[1]);             \
    A[2] = fma2(W, Xb.x, A[2]);             \
    A[3] = fma2(W, Xb.y, A[3]);

__global__ __launch_bounds__(256, 2)
void lstm_main(const float* __restrict__ Wo, const float* __restrict__ bo,
               float* __restrict__ out, int T) {
    extern __shared__ __align__(16) unsigned char smem_raw[];
    Smem* sm = reinterpret_cast<Smem*>(smem_raw);

    const int tid = threadIdx.x;
    const int j = tid & 63;
    const int y = tid >> 6;
    const int bb0 = blockIdx.x * 32;
    const int bthr = bb0 + y * 8;

    float c0[8], c1[8], c2[8], c3[8];

    // init h/c from embed, x from [0.5, 0.5, 0]
    #pragma unroll
    for (int i = 0; i < 8; i++) {
        const float* gi = g_init + (size_t)(bthr + i) * 128;
        float hv = gi[j];
        float cv = gi[64 + j];
        int pos = ((y * 8 + i) + 8 * (j & 3)) & 31;
        sm->h[0][j][pos] = hv; sm->h[1][j][pos] = hv;
        sm->h[2][j][pos] = hv; sm->h[3][j][pos] = hv;
        c0[i] = cv; c1[i] = cv; c2[i] = cv; c3[i] = cv;
    }
    if (tid < 96) {
        int kx = tid >> 5, b = tid & 31;
        sm->x[kx][b] = (kx == 2) ? 0.f : 0.5f;
    }

    // prime the weight pipeline (chunks 0, 1)
    prefetch_chunk(sm, 0, tid);
    prefetch_chunk(sm, 1, tid);
    __syncthreads();

    const float4* BIA = ((const float4*)g_bias) + j;  // + l*64
    const float4* WI0 = ((const float4*)g_wih0) + j;  // + kx*64
    const int base_rb = y * 8;

    for (int t = 0; t < T; t++) {
        #pragma unroll
        for (int l = 0; l < 4; l++) {
            float4 bv = BIA[l * 64];
            ull a0[4], a1[4], a2[4], a3[4];
            {
                ull s0 = splat2(bv.x), s1 = splat2(bv.y), s2 = splat2(bv.z), s3 = splat2(bv.w);
                #pragma unroll
                for (int p = 0; p < 4; p++) { a0[p] = s0; a1[p] = s1; a2[p] = s2; a3[p] = s3; }
            }
            if (l == 0) {
                // input part: x (3 features)  (x_s valid: written before last barrier)
                #pragma unroll
                for (int kx = 0; kx < 3; kx++) {
                    float4 wi = WI0[kx * 64];
                    const ulonglong2* xp = (const ulonglong2*)&sm->x[kx][base_rb];
                    ulonglong2 xa = xp[0], xb = xp[1];
                    ull w;
                    w = splat2(wi.x); FMA2_BCAST(a0, w, xa, xb);
                    w = splat2(wi.y); FMA2_BCAST(a1, w, xa, xb);
                    w = splat2(wi.z); FMA2_BCAST(a2, w, xa, xb);
                    w = splat2(wi.w); FMA2_BCAST(a3, w, xa, xb);
                }
            }

            for (int c = 0; c < NCHUNK_PER_LAYER; c++) {
                const int gc = l * NCHUNK_PER_LAYER + c;
                asm volatile("cp.async.wait_group 1;" ::: "memory");
                __syncthreads();   // chunk gc staged & visible; h writes of prev layer visible

                const int pb = gc & 1;
                const float4* WH = &sm->wbuf[pb][0][0][j];
                const float4* WI = &sm->wbuf[pb][1][0][j];
                const int k0 = c * CHUNK_K;

                if (l == 0) {
                    #pragma unroll 4
                    for (int kk = 0; kk < CHUNK_K; kk++) {
                        float4 wh = WH[kk * 64];
                        int rb = (base_rb + 8 * (kk & 3)) & 31;
                        const ulonglong2* hp = (const ulonglong2*)&sm->h[0][k0 + kk][rb];
                        ulonglong2 ha = hp[0], hb = hp[1];
                        ull w;
                        w = splat2(wh.x); FMA2_BCAST(a0, w, ha, hb);
                        w = splat2(wh.y); FMA2_BCAST(a1, w, ha, hb);
                        w = splat2(wh.z); FMA2_BCAST(a2, w, ha, hb);
                        w = splat2(wh.w); FMA2_BCAST(a3, w, ha, hb);
                    }
                } else {
                    #pragma unroll 4
                    for (int kk = 0; kk < CHUNK_K; kk++) {
                        float4 wh = WH[kk * 64];
                        float4 wi = WI[kk * 64];
                        int rb = (base_rb + 8 * (kk & 3)) & 31;
                        const ulonglong2* hp = (const ulonglong2*)&sm->h[l][k0 + kk][rb];
                        const ulonglong2* ip = (const ulonglong2*)&sm->h[l - 1][k0 + kk][rb];
                        ulonglong2 ha = hp[0], hb = hp[1];
                        ulonglong2 xa = ip[0], xb = ip[1];
                        ull w;
                        w = splat2(wh.x); FMA2_BCAST(a0, w, ha, hb);
                        w = splat2(wh.y); FMA2_BCAST(a1, w, ha, hb);
                        w = splat2(wh.z); FMA2_BCAST(a2, w, ha, hb);
                        w = splat2(wh.w); FMA2_BCAST(a3, w, ha, hb);
                        w = splat2(wi.x); FMA2_BCAST(a0, w, xa, xb);
                        w = splat2(wi.y); FMA2_BCAST(a1, w, xa, xb);
                        w = splat2(wi.z); FMA2_BCAST(a2, w, xa, xb);
                        w = splat2(wi.w); FMA2_BCAST(a3, w, xa, xb);
                    }
                }
                __syncthreads();   // all reads of wbuf[pb] (and h for this chunk) done
                prefetch_chunk(sm, (gc + 2) & (NCHUNK_TOTAL - 1), tid);
            }

            // gate nonlinearities + h/c update
            const int wbase = (base_rb + 8 * (j & 3)) & 31;
            #define DO_UPDATE(C)                                                        \
            {                                                                           \
                _Pragma("unroll")                                                       \
                for (int p = 0; p < 4; p++) {                                           \
                    float2 iv = u2f(a0[p]), fv = u2f(a1[p]);                            \
                    float2 gv = u2f(a2[p]), ov = u2f(a3[p]);                            \
                    float cn0 = sigm(fv.x) * C[2 * p]     + sigm(iv.x) * tanh_(gv.x);   \
                    float cn1 = sigm(fv.y) * C[2 * p + 1] + sigm(iv.y) * tanh_(gv.y);   \
                    C[2 * p] = cn0; C[2 * p + 1] = cn1;                                 \
                    sm->h[l][j][wbase + 2 * p]     = sigm(ov.x) * tanh_(cn0);           \
                    sm->h[l][j][wbase + 2 * p + 1] = sigm(ov.y) * tanh_(cn1);           \
                }                                                                       \
            }
            if (l == 0)      DO_UPDATE(c0)
            else if (l == 1) DO_UPDATE(c1)
            else if (l == 2) DO_UPDATE(c2)
            else             DO_UPDATE(c3)
            #undef DO_UPDATE
        }
        __syncthreads();   // h[3] update visible to pred readers

        // pred = h[3] @ Wo.T + bo  (96 threads: (jo, b))
        if (tid < 96) {
            int b = tid & 31, jo = tid >> 5;
            float acc = __ldg(&bo[jo]);
            #pragma unroll 4
            for (int k = 0; k < 64; k++) {
                acc += __ldg(&Wo[jo * 64 + k]) * sm->h[3][k][(b + 8 * (k & 3)) & 31];
            }
            sm->x[jo][b] = acc;
            out[(size_t)(bb0 + b) * (3 * T) + t * 3 + jo] = acc;
        }
        __syncthreads();  // x ready for next step's layer 0
    }
}

// ---------------- entry ----------------
extern "C" void kernel_launch(void* const* d_in, const int* in_sizes, int n_in,
                              void* d_out, int out_size) {
    const float* conds     = (const float*)d_in[0];
    const float* W1        = (const float*)d_in[1];
    const float* b1        = (const float*)d_in[2];
    const float* W2        = (const float*)d_in[3];
    const float* b2        = (const float*)d_in[4];
    const float* W_ih0     = (const float*)d_in[5];
    const float* W_ih_rest = (const float*)d_in[6];
    const float* W_hh      = (const float*)d_in[7];
    const float* b_ih      = (const float*)d_in[8];
    const float* b_hh      = (const float*)d_in[9];
    const float* Wo        = (const float*)d_in[10];
    const float* bo        = (const float*)d_in[11];

    int B = in_sizes[0] / 8;
    if (B > B_MAX) B = B_MAX;
    int T = out_size / (B * 3);

    // dynamic smem (66 KB/CTA > 48 KB static limit; 2 CTAs/SM = 132 KB <= 228 KB)
    cudaFuncSetAttribute(lstm_main, cudaFuncAttributeMaxDynamicSharedMemorySize,
                         (int)sizeof(Smem));

    const int total_repack = 4 * 256 * 64 + 3 * 256 * 64 + 256 * 3 + 4 * 256;
    repack_k<<<(total_repack + 255) / 256, 256>>>(W_ih0, W_ih_rest, W_hh, b_ih, b_hh);
    embed_k<<<B, 128>>>(conds, W1, b1, W2, b2);
    lstm_main<<<B / 32, 256, sizeof(Smem)>>>(Wo, bo, (float*)d_out, T);
}

// round 7
// speedup vs baseline: 1.4660x; 1.4655x over previous
#include <cuda_runtime.h>
#include <cuda_bf16.h>
#include <cstdint>

#define B_MAX 65536

// ---------------- device scratch (no allocs allowed) ----------------
// repacked weights: [l][hi/lo][n'=4j+gate : 256][k : 136 (128 + pad)] bf16
__device__ __align__(16) __nv_bfloat16 g_wm[4][2][256][136];
__device__ float g_init[(size_t)B_MAX * 128];   // [b][128] = (h0 | c0)

// ---------------- math ----------------
__device__ __forceinline__ float sigm(float x) { return __fdividef(1.f, 1.f + __expf(-x)); }
__device__ __forceinline__ float tanh_(float x) {
    float ax = fabsf(x);
    float e = __expf(-2.f * ax);
    return copysignf(__fdividef(1.f - e, 1.f + e), x);
}

// ---------------- PTX helpers (all portable: sm_80+) ----------------
__device__ __forceinline__ uint32_t s32(const void* p) { return (uint32_t)__cvta_generic_to_shared(p); }
__device__ __forceinline__ void cp16(uint32_t dst, const void* src) {
    asm volatile("cp.async.cg.shared.global [%0], [%1], 16;" :: "r"(dst), "l"(src));
}
__device__ __forceinline__ void cp_commit() { asm volatile("cp.async.commit_group;" ::: "memory"); }
__device__ __forceinline__ void cp_wait0()  { asm volatile("cp.async.wait_group 0;" ::: "memory"); }

__device__ __forceinline__ void ldsm4(uint32_t r[4], uint32_t addr) {
    asm volatile("ldmatrix.sync.aligned.m8n8.x4.shared.b16 {%0,%1,%2,%3}, [%4];"
        : "=r"(r[0]), "=r"(r[1]), "=r"(r[2]), "=r"(r[3]) : "r"(addr));
}
__device__ __forceinline__ void mma16816(float d[4], const uint32_t a[4], uint32_t b0, uint32_t b1) {
    asm volatile("mma.sync.aligned.m16n8k16.row.col.f32.bf16.bf16.f32 "
        "{%0,%1,%2,%3}, {%4,%5,%6,%7}, {%8,%9}, {%0,%1,%2,%3};"
        : "+f"(d[0]), "+f"(d[1]), "+f"(d[2]), "+f"(d[3])
        : "r"(a[0]), "r"(a[1]), "r"(a[2]), "r"(a[3]), "r"(b0), "r"(b1));
}

// ---------------- SMEM layout (bytes from 1024-aligned base) ----------------
// hHi/hLo: [l:4][m(batch):64][k(j):72] bf16 (144B rows, 16B aligned, conflict-free ldmatrix)
#define OFF_HHI  0        // 36864
#define OFF_HLO  36864    // 36864
#define OFF_W    73728    // [256][136] bf16 = 69632 (272B rows)
#define OFF_GT   143360   // Gt[n':256][m:66 pad] f32 = 67584
#define OFF_BIAS 210944   // [4][256] f32 = 4096
#define OFF_WI0  215040   // [256][3] f32 = 3072
#define OFF_WO   218112   // [3][64] f32 = 768
#define OFF_BO   218880   // 16
#define OFF_X    218896   // [3][64] f32 = 768
#define SMEM_USE 219664
#define SMEM_REQ (SMEM_USE + 1024)

// ---------------- prologue 1: weight repack (bf16 hi/lo, gate-interleaved cols) ----------------
// n' = 4*j + gate  (gate order i,f,g,o);  k<64: W_hh[l][g*64+j][k]; k>=64: W_ih_rest[l-1][..][k-64] (0 for l==0)
__global__ void repack_k(const float* __restrict__ W_hh, const float* __restrict__ W_ih_rest) {
    int idx = blockIdx.x * blockDim.x + threadIdx.x;
    if (idx >= 4 * 256 * 136) return;
    int kc = idx % 136, r = (idx / 136) & 255, l = idx / (136 * 256);
    float v = 0.f;
    if (kc < 128) {
        int j = r >> 2, g = r & 3, n = g * 64 + j;
        if (kc < 64)      v = W_hh[(l * 256 + n) * 64 + kc];
        else if (l > 0)   v = W_ih_rest[((l - 1) * 256 + n) * 64 + (kc - 64)];
    }
    __nv_bfloat16 hi = __float2bfloat16(v);
    __nv_bfloat16 lo = __float2bfloat16(v - __bfloat162float(hi));
    g_wm[l][0][r][kc] = hi;
    g_wm[l][1][r][kc] = lo;
}

// ---------------- prologue 2: decoder_fc -> (h0|c0) ----------------
__global__ void embed_k(const float* __restrict__ conds,
                        const float* __restrict__ W1, const float* __restrict__ b1,
                        const float* __restrict__ W2, const float* __restrict__ b2) {
    int b = blockIdx.x;
    __shared__ float hid[64];
    __shared__ float cnd[8];
    int t = threadIdx.x;  // 128
    if (t < 8) cnd[t] = conds[b * 8 + t];
    __syncthreads();
    if (t < 64) {
        float a = b1[t];
        #pragma unroll
        for (int k = 0; k < 8; k++) a += cnd[k] * W1[t * 8 + k];
        hid[t] = fmaxf(a, 0.f);
    }
    __syncthreads();
    float a = b2[t];
    #pragma unroll
    for (int k = 0; k < 64; k++) a += hid[k] * W2[t * 64 + k];
    g_init[(size_t)b * 128 + t] = a;
}

// stage weight image (l, hi/lo) into SMEM W buffer: 69632B contiguous
__device__ __forceinline__ void stageW(uint32_t wS, int l, int hl, int tid) {
    const char* src = (const char*)&g_wm[l][hl][0][0];
    #pragma unroll
    for (int n = 0; n < 17; n++)
        cp16(wS + (uint32_t)(tid * 16 + n * 4096), src + tid * 16 + n * 4096);
    cp_commit();
}

// one K=64 block of MMAs: A from h block at ABASE (rows=batch, 144B stride),
// W k-columns starting at kstep KS0 (16 k per step)
#define CHUNK(ABASE, KS0)                                                              \
{                                                                                      \
    _Pragma("unroll")                                                                  \
    for (int ki = 0; ki < 4; ki++) {                                                   \
        uint32_t af_[2][4];                                                            \
        _Pragma("unroll")                                                              \
        for (int mt = 0; mt < 2; mt++)                                                 \
            ldsm4(af_[mt], (ABASE) + (uint32_t)((m0w + mt * 16) * 144 + ki * 32) + a_laneoff); \
        _Pragma("unroll")                                                              \
        for (int np = 0; np < 4; np++) {                                               \
            uint32_t bf_[4];                                                           \
            ldsm4(bf_, wS + (uint32_t)((n0w + np * 16) * 272 + ((KS0) + ki) * 32) + b_laneoff); \
            _Pragma("unroll")                                                          \
            for (int mt = 0; mt < 2; mt++) {                                           \
                mma16816(acc[mt][2 * np],     af_[mt], bf_[0], bf_[2]);                \
                mma16816(acc[mt][2 * np + 1], af_[mt], bf_[1], bf_[3]);                \
            }                                                                          \
        }                                                                              \
    }                                                                                  \
}

// epilogue for layer L with c-register array CR (compile-time L via switch)
#define EPI(L, CR)                                                                     \
{                                                                                      \
    float x0 = 0.f, x1 = 0.f, x2 = 0.f;                                                \
    if ((L) == 0) { x0 = xS[b]; x1 = xS[64 + b]; x2 = xS[128 + b]; }                   \
    _Pragma("unroll")                                                                  \
    for (int jj = 0; jj < 16; jj++) {                                                  \
        int j = jg * 16 + jj;                                                          \
        float vi = GtS[(4 * j + 0) * 66 + b] + biasS[(L) * 256 + j];                   \
        float vf = GtS[(4 * j + 1) * 66 + b] + biasS[(L) * 256 + 64 + j];              \
        float vg = GtS[(4 * j + 2) * 66 + b] + biasS[(L) * 256 + 128 + j];             \
        float vo = GtS[(4 * j + 3) * 66 + b] + biasS[(L) * 256 + 192 + j];             \
        if ((L) == 0) {                                                                \
            vi += x0 * wi0S[j * 3] + x1 * wi0S[j * 3 + 1] + x2 * wi0S[j * 3 + 2];      \
            vf += x0 * wi0S[(64 + j) * 3] + x1 * wi0S[(64 + j) * 3 + 1] + x2 * wi0S[(64 + j) * 3 + 2];   \
            vg += x0 * wi0S[(128 + j) * 3] + x1 * wi0S[(128 + j) * 3 + 1] + x2 * wi0S[(128 + j) * 3 + 2]; \
            vo += x0 * wi0S[(192 + j) * 3] + x1 * wi0S[(192 + j) * 3 + 1] + x2 * wi0S[(192 + j) * 3 + 2]; \
        }                                                                              \
        float cn = sigm(vf) * CR[jj] + sigm(vi) * tanh_(vg);                           \
        CR[jj] = cn;                                                                   \
        float hn = sigm(vo) * tanh_(cn);                                               \
        __nv_bfloat16 bh = __float2bfloat16(hn);                                       \
        __nv_bfloat16 bl = __float2bfloat16(hn - __bfloat162float(bh));                \
        hHiE[((L) * 64 + b) * 72 + j] = bh;                                            \
        hLoE[((L) * 64 + b) * 72 + j] = bl;                                            \
    }                                                                                  \
}

__global__ __launch_bounds__(256)
void lstm_main(const float* __restrict__ b_ih, const float* __restrict__ b_hh,
               const float* __restrict__ W_ih0,
               const float* __restrict__ Wo, const float* __restrict__ bo,
               float* __restrict__ out, int T) {
    extern __shared__ char raw[];
    char* basep = (char*)(((uintptr_t)raw + 1023) & ~(uintptr_t)1023);
    const uint32_t hHiS = s32(basep + OFF_HHI);
    const uint32_t hLoS = s32(basep + OFF_HLO);
    const uint32_t wS   = s32(basep + OFF_W);
    __nv_bfloat16* hHiE = (__nv_bfloat16*)(basep + OFF_HHI);
    __nv_bfloat16* hLoE = (__nv_bfloat16*)(basep + OFF_HLO);
    float* GtS   = (float*)(basep + OFF_GT);
    float* biasS = (float*)(basep + OFF_BIAS);
    float* wi0S  = (float*)(basep + OFF_WI0);
    float* woS   = (float*)(basep + OFF_WO);
    float* boS   = (float*)(basep + OFF_BO);
    float* xS    = (float*)(basep + OFF_X);

    const int tid = threadIdx.x;
    const int lane = tid & 31, wid = tid >> 5;
    const int b = tid & 63, jg = tid >> 6;          // epilogue mapping
    const int bb0 = blockIdx.x * 64;

    // warp tiling: 2 (M) x 4 (N)
    const int m0w = (wid & 1) * 32;
    const int n0w = (wid >> 1) * 64;
    const int sel = lane >> 3, lrow = lane & 7;
    const uint32_t a_laneoff = (uint32_t)(((sel & 1) * 8 + lrow) * 144 + (sel >> 1) * 16);
    const uint32_t b_laneoff = (uint32_t)(((sel & 1) * 8 + lrow) * 272 + (sel >> 1) * 16);
    const int gid = lane >> 2, tig = lane & 3;

    // ---- stage small params ----
    for (int i = tid; i < 1024; i += 256) biasS[i] = b_ih[i] + b_hh[i];
    for (int i = tid; i < 768;  i += 256) wi0S[i] = W_ih0[i];
    if (tid < 192) woS[tid] = Wo[tid];
    if (tid < 3)   boS[tid] = bo[tid];
    if (tid < 64)  { xS[tid] = 0.5f; xS[64 + tid] = 0.5f; xS[128 + tid] = 0.f; }

    // ---- init h (bf16 hi/lo, all layers) and c (fp32 regs) ----
    float cr0[16], cr1[16], cr2[16], cr3[16];
    #pragma unroll
    for (int jj = 0; jj < 16; jj++) {
        int j = jg * 16 + jj;
        float hv = g_init[(size_t)(bb0 + b) * 128 + j];
        float cv = g_init[(size_t)(bb0 + b) * 128 + 64 + j];
        cr0[jj] = cv; cr1[jj] = cv; cr2[jj] = cv; cr3[jj] = cv;
        __nv_bfloat16 bh = __float2bfloat16(hv);
        __nv_bfloat16 bl = __float2bfloat16(hv - __bfloat162float(bh));
        #pragma unroll
        for (int l = 0; l < 4; l++) {
            hHiE[(l * 64 + b) * 72 + j] = bh;
            hLoE[(l * 64 + b) * 72 + j] = bl;
        }
    }
    stageW(wS, 0, 0, tid);   // prefetch Whi(layer 0)

    for (int t = 0; t < T; t++) {
        for (int l = 0; l < 4; l++) {
            cp_wait0();
            __syncthreads();           // Whi(l) staged; h writes from prev layer visible

            float acc[2][8][4];
            #pragma unroll
            for (int mt = 0; mt < 2; mt++)
                #pragma unroll
                for (int nt = 0; nt < 8; nt++)
                    #pragma unroll
                    for (int q = 0; q < 4; q++) acc[mt][nt][q] = 0.f;

            for (int p = 0; p < 3; p++) {
                if (p == 2) {          // Whi reads done by all warps -> restage with Wlo
                    __syncthreads();
                    stageW(wS, l, 1, tid);
                    cp_wait0();
                    __syncthreads();
                }
                const uint32_t ab = (p == 1) ? hLoS : hHiS;
                CHUNK(ab + (uint32_t)(l * 9216), 0);          // recurrent half (k 0..63)
                if (l > 0) CHUNK(ab + (uint32_t)((l - 1) * 9216), 4);  // input half (k 64..127)
            }

            // write gate pre-activations, transposed: Gt[n'][m]
            #pragma unroll
            for (int mt = 0; mt < 2; mt++)
                #pragma unroll
                for (int nt = 0; nt < 8; nt++) {
                    int col = n0w + nt * 8 + 2 * tig;
                    int row = m0w + mt * 16 + gid;
                    GtS[col * 66 + row]           = acc[mt][nt][0];
                    GtS[(col + 1) * 66 + row]     = acc[mt][nt][1];
                    GtS[col * 66 + row + 8]       = acc[mt][nt][2];
                    GtS[(col + 1) * 66 + row + 8] = acc[mt][nt][3];
                }
            __syncthreads();           // Gt complete; Wlo reads done -> buffer free

            // prefetch next layer's Whi under the epilogue
            if (!(t == T - 1 && l == 3)) stageW(wS, (l + 1) & 3, 0, tid);

            switch (l) {
                case 0: EPI(0, cr0); break;
                case 1: EPI(1, cr1); break;
                case 2: EPI(2, cr2); break;
                default: EPI(3, cr3); break;
            }

            if (l == 3) {
                __syncthreads();       // h3 visible for pred
                if (tid < 192) {
                    int jo = tid >> 6;
                    float a = boS[jo];
                    #pragma unroll 8
                    for (int j = 0; j < 64; j++)
                        a += woS[jo * 64 + j] *
                             (__bfloat162float(hHiE[(192 + b) * 72 + j]) +
                              __bfloat162float(hLoE[(192 + b) * 72 + j]));
                    out[(size_t)(bb0 + b) * (3 * T) + (size_t)t * 3 + jo] = a;
                    xS[jo * 64 + b] = a;
                }
            }
        }
    }
}

// ---------------- entry ----------------
extern "C" void kernel_launch(void* const* d_in, const int* in_sizes, int n_in,
                              void* d_out, int out_size) {
    const float* conds     = (const float*)d_in[0];
    const float* W1        = (const float*)d_in[1];
    const float* b1        = (const float*)d_in[2];
    const float* W2        = (const float*)d_in[3];
    const float* b2        = (const float*)d_in[4];
    const float* W_ih0     = (const float*)d_in[5];
    const float* W_ih_rest = (const float*)d_in[6];
    const float* W_hh      = (const float*)d_in[7];
    const float* b_ih      = (const float*)d_in[8];
    const float* b_hh      = (const float*)d_in[9];
    const float* Wo        = (const float*)d_in[10];
    const float* bo        = (const float*)d_in[11];

    int B = in_sizes[0] / 8;
    if (B > B_MAX) B = B_MAX;
    int T = out_size / (B * 3);

    cudaFuncSetAttribute(lstm_main, cudaFuncAttributeMaxDynamicSharedMemorySize, SMEM_REQ);

    repack_k<<<(4 * 256 * 136 + 255) / 256, 256>>>(W_hh, W_ih_rest);
    embed_k<<<B, 128>>>(conds, W1, b1, W2, b2);
    lstm_main<<<B / 64, 256, SMEM_REQ>>>(b_ih, b_hh, W_ih0, Wo, bo, (float*)d_out, T);
}

// round 8
// speedup vs baseline: 1.8634x; 1.2710x over previous
#include <cuda_runtime.h>
#include <cuda_fp16.h>
#include <cstdint>

#define B_MAX 65536

// ---------------- device scratch (no allocs allowed) ----------------
// repacked weights (single fp16 image): [l][n'=4j+gate : 256][k : 136 (128+pad)]
__device__ __align__(16) __half g_wm[4][256][136];
__device__ float g_init[(size_t)B_MAX * 128];   // [b][128] = (h0 | c0)

// ---------------- math ----------------
__device__ __forceinline__ float sigm(float x) { return __fdividef(1.f, 1.f + __expf(-x)); }
__device__ __forceinline__ float tanh_(float x) {
    float ax = fabsf(x);
    float e = __expf(-2.f * ax);
    return copysignf(__fdividef(1.f - e, 1.f + e), x);
}

// ---------------- PTX helpers (portable sm_80+) ----------------
__device__ __forceinline__ uint32_t s32(const void* p) { return (uint32_t)__cvta_generic_to_shared(p); }
__device__ __forceinline__ void cp16(uint32_t dst, const void* src) {
    asm volatile("cp.async.cg.shared.global [%0], [%1], 16;" :: "r"(dst), "l"(src));
}
__device__ __forceinline__ void cp_commit() { asm volatile("cp.async.commit_group;" ::: "memory"); }
__device__ __forceinline__ void cp_wait0()  { asm volatile("cp.async.wait_group 0;" ::: "memory"); }

__device__ __forceinline__ void ldsm4(uint32_t r[4], uint32_t addr) {
    asm volatile("ldmatrix.sync.aligned.m8n8.x4.shared.b16 {%0,%1,%2,%3}, [%4];"
        : "=r"(r[0]), "=r"(r[1]), "=r"(r[2]), "=r"(r[3]) : "r"(addr));
}
__device__ __forceinline__ void mma16816(float d[4], const uint32_t a[4], uint32_t b0, uint32_t b1) {
    asm volatile("mma.sync.aligned.m16n8k16.row.col.f32.f16.f16.f32 "
        "{%0,%1,%2,%3}, {%4,%5,%6,%7}, {%8,%9}, {%0,%1,%2,%3};"
        : "+f"(d[0]), "+f"(d[1]), "+f"(d[2]), "+f"(d[3])
        : "r"(a[0]), "r"(a[1]), "r"(a[2]), "r"(a[3]), "r"(b0), "r"(b1));
}

// ---------------- SMEM layout (bytes from 1024-aligned base) ----------------
// hHi/hLo: [l:4][m(batch):64][k(j):72] fp16 (144B rows, conflict-free ldmatrix)
#define OFF_HHI  0        // 36864
#define OFF_HLO  36864    // 36864
#define OFF_W    73728    // [256][136] fp16 = 69632 (272B rows)
#define OFF_GT   143360   // Gt[n':256][m:66 pad] f32 = 67584
#define OFF_BIAS 210944   // [4][256] f32 = 4096
#define OFF_WI0  215040   // [256][3] f32 = 3072
#define OFF_WO   218112   // [3][64] f32 = 768
#define OFF_BO   218880   // 16
#define OFF_X    218896   // [3][64] f32 = 768
#define SMEM_USE 219664
#define SMEM_REQ (SMEM_USE + 1024)

// ---------------- prologue 1: weight repack (fp16, gate-interleaved cols) ----------------
// n' = 4*j + gate (i,f,g,o);  k<64: W_hh[l][g*64+j][k]; k>=64: W_ih_rest[l-1][..][k-64] (0 for l==0)
__global__ void repack_k(const float* __restrict__ W_hh, const float* __restrict__ W_ih_rest) {
    int idx = blockIdx.x * blockDim.x + threadIdx.x;
    if (idx >= 4 * 256 * 136) return;
    int kc = idx % 136, r = (idx / 136) & 255, l = idx / (136 * 256);
    float v = 0.f;
    if (kc < 128) {
        int j = r >> 2, g = r & 3, n = g * 64 + j;
        if (kc < 64)      v = W_hh[(l * 256 + n) * 64 + kc];
        else if (l > 0)   v = W_ih_rest[((l - 1) * 256 + n) * 64 + (kc - 64)];
    }
    g_wm[l][r][kc] = __float2half(v);
}

// ---------------- prologue 2: decoder_fc -> (h0|c0) ----------------
__global__ void embed_k(const float* __restrict__ conds,
                        const float* __restrict__ W1, const float* __restrict__ b1,
                        const float* __restrict__ W2, const float* __restrict__ b2) {
    int b = blockIdx.x;
    __shared__ float hid[64];
    __shared__ float cnd[8];
    int t = threadIdx.x;  // 128
    if (t < 8) cnd[t] = conds[b * 8 + t];
    __syncthreads();
    if (t < 64) {
        float a = b1[t];
        #pragma unroll
        for (int k = 0; k < 8; k++) a += cnd[k] * W1[t * 8 + k];
        hid[t] = fmaxf(a, 0.f);
    }
    __syncthreads();
    float a = b2[t];
    #pragma unroll
    for (int k = 0; k < 64; k++) a += hid[k] * W2[t * 64 + k];
    g_init[(size_t)b * 128 + t] = a;
}

// stage layer-l weight image into SMEM (69632 B)
__device__ __forceinline__ void stageW(uint32_t wS, int l, int tid) {
    const char* src = (const char*)&g_wm[l][0][0];
    #pragma unroll
    for (int n = 0; n < 17; n++)
        cp16(wS + (uint32_t)(tid * 16 + n * 4096), src + tid * 16 + n * 4096);
    cp_commit();
}

// One K=64 block: both passes (Ahi + Alo) with shared B fragments.
#define CHUNK2(AHI, ALO, KS0)                                                          \
{                                                                                      \
    _Pragma("unroll")                                                                  \
    for (int ki = 0; ki < 4; ki++) {                                                   \
        uint32_t ah_[2][4], al_[2][4];                                                 \
        _Pragma("unroll")                                                              \
        for (int mt = 0; mt < 2; mt++) {                                               \
            ldsm4(ah_[mt], (AHI) + (uint32_t)((m0w + mt * 16) * 144 + ki * 32) + a_laneoff); \
            ldsm4(al_[mt], (ALO) + (uint32_t)((m0w + mt * 16) * 144 + ki * 32) + a_laneoff); \
        }                                                                              \
        _Pragma("unroll")                                                              \
        for (int np = 0; np < 4; np++) {                                               \
            uint32_t bf_[4];                                                           \
            ldsm4(bf_, wS + (uint32_t)((n0w + np * 16) * 272 + ((KS0) + ki) * 32) + b_laneoff); \
            _Pragma("unroll")                                                          \
            for (int mt = 0; mt < 2; mt++) {                                           \
                mma16816(acc[mt][2 * np],     ah_[mt], bf_[0], bf_[2]);                \
                mma16816(acc[mt][2 * np + 1], ah_[mt], bf_[1], bf_[3]);                \
                mma16816(acc[mt][2 * np],     al_[mt], bf_[0], bf_[2]);                \
                mma16816(acc[mt][2 * np + 1], al_[mt], bf_[1], bf_[3]);                \
            }                                                                          \
        }                                                                              \
    }                                                                                  \
}

// epilogue for layer L with c-register array CR
#define EPI(L, CR)                                                                     \
{                                                                                      \
    float x0 = 0.f, x1 = 0.f, x2 = 0.f;                                                \
    if ((L) == 0) { x0 = xS[b]; x1 = xS[64 + b]; x2 = xS[128 + b]; }                   \
    _Pragma("unroll")                                                                  \
    for (int jj = 0; jj < 16; jj++) {                                                  \
        int j = jg * 16 + jj;                                                          \
        float vi = GtS[(4 * j + 0) * 66 + b] + biasS[(L) * 256 + j];                   \
        float vf = GtS[(4 * j + 1) * 66 + b] + biasS[(L) * 256 + 64 + j];              \
        float vg = GtS[(4 * j + 2) * 66 + b] + biasS[(L) * 256 + 128 + j];             \
        float vo = GtS[(4 * j + 3) * 66 + b] + biasS[(L) * 256 + 192 + j];             \
        if ((L) == 0) {                                                                \
            vi += x0 * wi0S[j * 3] + x1 * wi0S[j * 3 + 1] + x2 * wi0S[j * 3 + 2];      \
            vf += x0 * wi0S[(64 + j) * 3] + x1 * wi0S[(64 + j) * 3 + 1] + x2 * wi0S[(64 + j) * 3 + 2];   \
            vg += x0 * wi0S[(128 + j) * 3] + x1 * wi0S[(128 + j) * 3 + 1] + x2 * wi0S[(128 + j) * 3 + 2]; \
            vo += x0 * wi0S[(192 + j) * 3] + x1 * wi0S[(192 + j) * 3 + 1] + x2 * wi0S[(192 + j) * 3 + 2]; \
        }                                                                              \
        float cn = sigm(vf) * CR[jj] + sigm(vi) * tanh_(vg);                           \
        CR[jj] = cn;                                                                   \
        float hn = sigm(vo) * tanh_(cn);                                               \
        __half bh = __float2half(hn);                                                  \
        __half bl = __float2half(hn - __half2float(bh));                               \
        hHiE[((L) * 64 + b) * 72 + j] = bh;                                            \
        hLoE[((L) * 64 + b) * 72 + j] = bl;                                            \
    }                                                                                  \
}

__global__ __launch_bounds__(256)
void lstm_main(const float* __restrict__ b_ih, const float* __restrict__ b_hh,
               const float* __restrict__ W_ih0,
               const float* __restrict__ Wo, const float* __restrict__ bo,
               float* __restrict__ out, int T) {
    extern __shared__ char raw[];
    char* basep = (char*)(((uintptr_t)raw + 1023) & ~(uintptr_t)1023);
    const uint32_t hHiS = s32(basep + OFF_HHI);
    const uint32_t hLoS = s32(basep + OFF_HLO);
    const uint32_t wS   = s32(basep + OFF_W);
    __half* hHiE = (__half*)(basep + OFF_HHI);
    __half* hLoE = (__half*)(basep + OFF_HLO);
    float* GtS   = (float*)(basep + OFF_GT);
    float* biasS = (float*)(basep + OFF_BIAS);
    float* wi0S  = (float*)(basep + OFF_WI0);
    float* woS   = (float*)(basep + OFF_WO);
    float* boS   = (float*)(basep + OFF_BO);
    float* xS    = (float*)(basep + OFF_X);

    const int tid = threadIdx.x;
    const int lane = tid & 31, wid = tid >> 5;
    const int b = tid & 63, jg = tid >> 6;          // epilogue mapping
    const int bb0 = blockIdx.x * 64;

    // warp tiling: 2 (M) x 4 (N)
    const int m0w = (wid & 1) * 32;
    const int n0w = (wid >> 1) * 64;
    const int sel = lane >> 3, lrow = lane & 7;
    const uint32_t a_laneoff = (uint32_t)(((sel & 1) * 8 + lrow) * 144 + (sel >> 1) * 16);
    const uint32_t b_laneoff = (uint32_t)(((sel & 1) * 8 + lrow) * 272 + (sel >> 1) * 16);
    const int gid = lane >> 2, tig = lane & 3;

    // ---- stage small params ----
    for (int i = tid; i < 1024; i += 256) biasS[i] = b_ih[i] + b_hh[i];
    for (int i = tid; i < 768;  i += 256) wi0S[i] = W_ih0[i];
    if (tid < 192) woS[tid] = Wo[tid];
    if (tid < 3)   boS[tid] = bo[tid];
    if (tid < 64)  { xS[tid] = 0.5f; xS[64 + tid] = 0.5f; xS[128 + tid] = 0.f; }

    // ---- init h (fp16 hi/lo, all layers) and c (fp32 regs) ----
    float cr0[16], cr1[16], cr2[16], cr3[16];
    #pragma unroll
    for (int jj = 0; jj < 16; jj++) {
        int j = jg * 16 + jj;
        float hv = g_init[(size_t)(bb0 + b) * 128 + j];
        float cv = g_init[(size_t)(bb0 + b) * 128 + 64 + j];
        cr0[jj] = cv; cr1[jj] = cv; cr2[jj] = cv; cr3[jj] = cv;
        __half bh = __float2half(hv);
        __half bl = __float2half(hv - __half2float(bh));
        #pragma unroll
        for (int l = 0; l < 4; l++) {
            hHiE[(l * 64 + b) * 72 + j] = bh;
            hLoE[(l * 64 + b) * 72 + j] = bl;
        }
    }
    stageW(wS, 0, tid);   // prefetch W(layer 0)

    for (int t = 0; t < T; t++) {
        for (int l = 0; l < 4; l++) {
            cp_wait0();
            __syncthreads();           // W(l) staged; h writes from prev layer visible

            float acc[2][8][4];
            #pragma unroll
            for (int mt = 0; mt < 2; mt++)
                #pragma unroll
                for (int nt = 0; nt < 8; nt++)
                    #pragma unroll
                    for (int q = 0; q < 4; q++) acc[mt][nt][q] = 0.f;

            // recurrent half (k 0..63): A = h[l] (t-1)
            CHUNK2(hHiS + (uint32_t)(l * 9216), hLoS + (uint32_t)(l * 9216), 0);
            // input half (k 64..127): A = h[l-1] (fresh)
            if (l > 0)
                CHUNK2(hHiS + (uint32_t)((l - 1) * 9216), hLoS + (uint32_t)((l - 1) * 9216), 4);

            // write gate pre-activations, transposed: Gt[n'][m]
            #pragma unroll
            for (int mt = 0; mt < 2; mt++)
                #pragma unroll
                for (int nt = 0; nt < 8; nt++) {
                    int col = n0w + nt * 8 + 2 * tig;
                    int row = m0w + mt * 16 + gid;
                    GtS[col * 66 + row]           = acc[mt][nt][0];
                    GtS[(col + 1) * 66 + row]     = acc[mt][nt][1];
                    GtS[col * 66 + row + 8]       = acc[mt][nt][2];
                    GtS[(col + 1) * 66 + row + 8] = acc[mt][nt][3];
                }
            __syncthreads();           // Gt complete; W reads done -> buffer free

            // prefetch next layer's W under the epilogue
            if (!(t == T - 1 && l == 3)) stageW(wS, (l + 1) & 3, tid);

            switch (l) {
                case 0: EPI(0, cr0); break;
                case 1: EPI(1, cr1); break;
                case 2: EPI(2, cr2); break;
                default: EPI(3, cr3); break;
            }

            if (l == 3) {
                __syncthreads();       // h3 visible for pred
                if (tid < 192) {
                    int jo = tid >> 6;
                    float a = boS[jo];
                    #pragma unroll 8
                    for (int j = 0; j < 64; j++)
                        a += woS[jo * 64 + j] *
                             (__half2float(hHiE[(192 + b) * 72 + j]) +
                              __half2float(hLoE[(192 + b) * 72 + j]));
                    out[(size_t)(bb0 + b) * (3 * T) + (size_t)t * 3 + jo] = a;
                    xS[jo * 64 + b] = a;
                }
            }
        }
    }
}

// ---------------- entry ----------------
extern "C" void kernel_launch(void* const* d_in, const int* in_sizes, int n_in,
                              void* d_out, int out_size) {
    const float* conds     = (const float*)d_in[0];
    const float* W1        = (const float*)d_in[1];
    const float* b1        = (const float*)d_in[2];
    const float* W2        = (const float*)d_in[3];
    const float* b2        = (const float*)d_in[4];
    const float* W_ih0     = (const float*)d_in[5];
    const float* W_ih_rest = (const float*)d_in[6];
    const float* W_hh      = (const float*)d_in[7];
    const float* b_ih      = (const float*)d_in[8];
    const float* b_hh      = (const float*)d_in[9];
    const float* Wo        = (const float*)d_in[10];
    const float* bo        = (const float*)d_in[11];

    int B = in_sizes[0] / 8;
    if (B > B_MAX) B = B_MAX;
    int T = out_size / (B * 3);

    cudaFuncSetAttribute(lstm_main, cudaFuncAttributeMaxDynamicSharedMemorySize, SMEM_REQ);

    repack_k<<<(4 * 256 * 136 + 255) / 256, 256>>>(W_hh, W_ih_rest);
    embed_k<<<B, 128>>>(conds, W1, b1, W2, b2);
    lstm_main<<<B / 64, 256, SMEM_REQ>>>(b_ih, b_hh, W_ih0, Wo, bo, (float*)d_out, T);
}

// round 9
// speedup vs baseline: 1.9702x; 1.0573x over previous
#include <cuda_runtime.h>
#include <cuda_fp16.h>
#include <cstdint>

#define B_MAX 65536

// ---------------- device scratch (no allocs allowed) ----------------
// repacked weights (single fp16 image): [l][n'=4j+gate : 256][k : 136 (128+pad)]
__device__ __align__(16) __half g_wm[4][256][136];
__device__ float g_init[(size_t)B_MAX * 128];   // [b][128] = (h0 | c0)

// ---------------- math ----------------
__device__ __forceinline__ float sigm(float x) { return __fdividef(1.f, 1.f + __expf(-x)); }
__device__ __forceinline__ float tanh_(float x) {
    float ax = fabsf(x);
    float e = __expf(-2.f * ax);
    return copysignf(__fdividef(1.f - e, 1.f + e), x);
}

// ---------------- PTX helpers (portable sm_80+) ----------------
__device__ __forceinline__ uint32_t s32(const void* p) { return (uint32_t)__cvta_generic_to_shared(p); }
__device__ __forceinline__ void cp16(uint32_t dst, const void* src) {
    asm volatile("cp.async.cg.shared.global [%0], [%1], 16;" :: "r"(dst), "l"(src));
}
__device__ __forceinline__ void cp_commit() { asm volatile("cp.async.commit_group;" ::: "memory"); }
__device__ __forceinline__ void cp_wait0()  { asm volatile("cp.async.wait_group 0;" ::: "memory"); }

__device__ __forceinline__ void ldsm4(uint32_t r[4], uint32_t addr) {
    asm volatile("ldmatrix.sync.aligned.m8n8.x4.shared.b16 {%0,%1,%2,%3}, [%4];"
        : "=r"(r[0]), "=r"(r[1]), "=r"(r[2]), "=r"(r[3]) : "r"(addr));
}
__device__ __forceinline__ void mma16816(float d[4], const uint32_t a[4], uint32_t b0, uint32_t b1) {
    asm volatile("mma.sync.aligned.m16n8k16.row.col.f32.f16.f16.f32 "
        "{%0,%1,%2,%3}, {%4,%5,%6,%7}, {%8,%9}, {%0,%1,%2,%3};"
        : "+f"(d[0]), "+f"(d[1]), "+f"(d[2]), "+f"(d[3])
        : "r"(a[0]), "r"(a[1]), "r"(a[2]), "r"(a[3]), "r"(b0), "r"(b1));
}

#define BAR_ARRIVE(id, cnt) asm volatile("bar.arrive %0, %1;" :: "r"(id), "r"(cnt) : "memory")
#define BAR_SYNC(id, cnt)   asm volatile("bar.sync %0, %1;"   :: "r"(id), "r"(cnt) : "memory")

// ---------------- SMEM layout (bytes from 1024-aligned base) ----------------
#define OFF_HHI  0        // [l:4][m:64][k:72] fp16 = 36864
#define OFF_HLO  36864    // 36864
#define OFF_W    73728    // [256][136] fp16 = 69632 (272B rows)
#define OFF_GT   143360   // Gt[n':256][m:66 pad] f32 = 67584
#define OFF_BIAS 210944   // [4][256] f32 = 4096
#define OFF_WI0  215040   // [256][3] f32 = 3072
#define OFF_WO   218112   // [3][64] f32 = 768
#define OFF_BO   218880   // 16
#define OFF_X    218896   // [3][64] f32 = 768
#define SMEM_USE 219664
#define SMEM_REQ (SMEM_USE + 1024)

// ---------------- prologue 1: weight repack (fp16, gate-interleaved cols) ----------------
__global__ void repack_k(const float* __restrict__ W_hh, const float* __restrict__ W_ih_rest) {
    int idx = blockIdx.x * blockDim.x + threadIdx.x;
    if (idx >= 4 * 256 * 136) return;
    int kc = idx % 136, r = (idx / 136) & 255, l = idx / (136 * 256);
    float v = 0.f;
    if (kc < 128) {
        int j = r >> 2, g = r & 3, n = g * 64 + j;
        if (kc < 64)      v = W_hh[(l * 256 + n) * 64 + kc];
        else if (l > 0)   v = W_ih_rest[((l - 1) * 256 + n) * 64 + (kc - 64)];
    }
    g_wm[l][r][kc] = __float2half(v);
}

// ---------------- prologue 2: decoder_fc -> (h0|c0) ----------------
__global__ void embed_k(const float* __restrict__ conds,
                        const float* __restrict__ W1, const float* __restrict__ b1,
                        const float* __restrict__ W2, const float* __restrict__ b2) {
    int b = blockIdx.x;
    __shared__ float hid[64];
    __shared__ float cnd[8];
    int t = threadIdx.x;  // 128
    if (t < 8) cnd[t] = conds[b * 8 + t];
    __syncthreads();
    if (t < 64) {
        float a = b1[t];
        #pragma unroll
        for (int k = 0; k < 8; k++) a += cnd[k] * W1[t * 8 + k];
        hid[t] = fmaxf(a, 0.f);
    }
    __syncthreads();
    float a = b2[t];
    #pragma unroll
    for (int k = 0; k < 64; k++) a += hid[k] * W2[t * 64 + k];
    g_init[(size_t)b * 128 + t] = a;
}

// stage layer-l weight image into SMEM (69632 B) — MMA threads (tid<256) only
__device__ __forceinline__ void stageW(uint32_t wS, int l, int tid) {
    const char* src = (const char*)&g_wm[l][0][0];
    #pragma unroll
    for (int n = 0; n < 17; n++)
        cp16(wS + (uint32_t)(tid * 16 + n * 4096), src + tid * 16 + n * 4096);
    cp_commit();
}

// One K=64 block: both passes (Ahi + Alo) with shared B fragments.
#define CHUNK2(AHI, ALO, KS0)                                                          \
{                                                                                      \
    _Pragma("unroll")                                                                  \
    for (int ki = 0; ki < 4; ki++) {                                                   \
        uint32_t ah_[2][4], al_[2][4];                                                 \
        _Pragma("unroll")                                                              \
        for (int mt = 0; mt < 2; mt++) {                                               \
            ldsm4(ah_[mt], (AHI) + (uint32_t)((m0w + mt * 16) * 144 + ki * 32) + a_laneoff); \
            ldsm4(al_[mt], (ALO) + (uint32_t)((m0w + mt * 16) * 144 + ki * 32) + a_laneoff); \
        }                                                                              \
        _Pragma("unroll")                                                              \
        for (int np = 0; np < 4; np++) {                                               \
            uint32_t bf_[4];                                                           \
            ldsm4(bf_, wS + (uint32_t)((n0w + np * 16) * 272 + ((KS0) + ki) * 32) + b_laneoff); \
            _Pragma("unroll")                                                          \
            for (int mt = 0; mt < 2; mt++) {                                           \
                mma16816(acc[mt][2 * np],     ah_[mt], bf_[0], bf_[2]);                \
                mma16816(acc[mt][2 * np + 1], ah_[mt], bf_[1], bf_[3]);                \
                mma16816(acc[mt][2 * np],     al_[mt], bf_[0], bf_[2]);                \
                mma16816(acc[mt][2 * np + 1], al_[mt], bf_[1], bf_[3]);                \
            }                                                                          \
        }                                                                              \
    }                                                                                  \
}

// epilogue for layer L with c-register array CR (EPI threads: b, jg)
#define EPI(L, CR)                                                                     \
{                                                                                      \
    float x0 = 0.f, x1 = 0.f, x2 = 0.f;                                                \
    if ((L) == 0) { x0 = xS[b]; x1 = xS[64 + b]; x2 = xS[128 + b]; }                   \
    _Pragma("unroll")                                                                  \
    for (int jj = 0; jj < 16; jj++) {                                                  \
        int j = jg * 16 + jj;                                                          \
        float vi = GtS[(4 * j + 0) * 66 + b] + biasS[(L) * 256 + j];                   \
        float vf = GtS[(4 * j + 1) * 66 + b] + biasS[(L) * 256 + 64 + j];              \
        float vg = GtS[(4 * j + 2) * 66 + b] + biasS[(L) * 256 + 128 + j];             \
        float vo = GtS[(4 * j + 3) * 66 + b] + biasS[(L) * 256 + 192 + j];             \
        if ((L) == 0) {                                                                \
            vi += x0 * wi0S[j * 3] + x1 * wi0S[j * 3 + 1] + x2 * wi0S[j * 3 + 2];      \
            vf += x0 * wi0S[(64 + j) * 3] + x1 * wi0S[(64 + j) * 3 + 1] + x2 * wi0S[(64 + j) * 3 + 2];   \
            vg += x0 * wi0S[(128 + j) * 3] + x1 * wi0S[(128 + j) * 3 + 1] + x2 * wi0S[(128 + j) * 3 + 2]; \
            vo += x0 * wi0S[(192 + j) * 3] + x1 * wi0S[(192 + j) * 3 + 1] + x2 * wi0S[(192 + j) * 3 + 2]; \
        }                                                                              \
        float cn = sigm(vf) * CR[jj] + sigm(vi) * tanh_(vg);                           \
        CR[jj] = cn;                                                                   \
        float hn = sigm(vo) * tanh_(cn);                                               \
        __half bh = __float2half(hn);                                                  \
        __half bl = __float2half(hn - __half2float(bh));                               \
        hHiE[((L) * 64 + b) * 72 + j] = bh;                                            \
        hLoE[((L) * 64 + b) * 72 + j] = bl;                                            \
    }                                                                                  \
}

__global__ __launch_bounds__(512, 1)
void lstm_main(const float* __restrict__ b_ih, const float* __restrict__ b_hh,
               const float* __restrict__ W_ih0,
               const float* __restrict__ Wo, const float* __restrict__ bo,
               float* __restrict__ out, int T) {
    extern __shared__ char raw[];
    char* basep = (char*)(((uintptr_t)raw + 1023) & ~(uintptr_t)1023);
    const uint32_t hHiS = s32(basep + OFF_HHI);
    const uint32_t hLoS = s32(basep + OFF_HLO);
    const uint32_t wS   = s32(basep + OFF_W);
    __half* hHiE = (__half*)(basep + OFF_HHI);
    __half* hLoE = (__half*)(basep + OFF_HLO);
    float* GtS   = (float*)(basep + OFF_GT);
    float* biasS = (float*)(basep + OFF_BIAS);
    float* wi0S  = (float*)(basep + OFF_WI0);
    float* woS   = (float*)(basep + OFF_WO);
    float* boS   = (float*)(basep + OFF_BO);
    float* xS    = (float*)(basep + OFF_X);

    const int tid = threadIdx.x;
    const int bb0 = blockIdx.x * 64;

    // ---- stage small params (all 512 threads) ----
    for (int i = tid; i < 1024; i += 512) biasS[i] = b_ih[i] + b_hh[i];
    for (int i = tid; i < 768;  i += 512) wi0S[i] = W_ih0[i];
    if (tid < 192) woS[tid] = Wo[tid];
    if (tid < 3)   boS[tid] = bo[tid];
    if (tid < 64)  { xS[tid] = 0.5f; xS[64 + tid] = 0.5f; xS[128 + tid] = 0.f; }

    // c-state lives in EPI warps (tid >= 256)
    float cr0[16], cr1[16], cr2[16], cr3[16];
    if (tid >= 256) {
        const int etid = tid - 256;
        const int b = etid & 63, jg = etid >> 6;
        #pragma unroll
        for (int jj = 0; jj < 16; jj++) {
            int j = jg * 16 + jj;
            float hv = g_init[(size_t)(bb0 + b) * 128 + j];
            float cv = g_init[(size_t)(bb0 + b) * 128 + 64 + j];
            cr0[jj] = cv; cr1[jj] = cv; cr2[jj] = cv; cr3[jj] = cv;
            __half bh = __float2half(hv);
            __half bl = __float2half(hv - __half2float(bh));
            #pragma unroll
            for (int l = 0; l < 4; l++) {
                hHiE[(l * 64 + b) * 72 + j] = bh;
                hLoE[(l * 64 + b) * 72 + j] = bl;
            }
        }
    }
    if (tid < 256) stageW(wS, 0, tid);   // prefetch W(layer 0)
    __syncthreads();

    if (tid < 256) {
        // ================= MMA group (warps 0-7) =================
        const int lane = tid & 31, wid = tid >> 5;
        const int m0w = (wid & 1) * 32;
        const int n0w = (wid >> 1) * 64;
        const int sel = lane >> 3, lrow = lane & 7;
        const uint32_t a_laneoff = (uint32_t)(((sel & 1) * 8 + lrow) * 144 + (sel >> 1) * 16);
        const uint32_t b_laneoff = (uint32_t)(((sel & 1) * 8 + lrow) * 272 + (sel >> 1) * 16);
        const int gid = lane >> 2, tig = lane & 3;

        for (int t = 0; t < T; t++) {
            for (int l = 0; l < 4; l++) {
                cp_wait0();
                BAR_SYNC(3, 256);           // W(l) fully staged (all MMA warps)

                float acc[2][8][4];
                #pragma unroll
                for (int mt = 0; mt < 2; mt++)
                    #pragma unroll
                    for (int nt = 0; nt < 8; nt++)
                        #pragma unroll
                        for (int q = 0; q < 4; q++) acc[mt][nt][q] = 0.f;

                // recurrent half: A = h[l] (t-1) — independent of EPI(l-1)
                CHUNK2(hHiS + (uint32_t)(l * 9216), hLoS + (uint32_t)(l * 9216), 0);

                BAR_SYNC(2, 512);           // EPI(l-1) done: h[l-1] fresh, Gt free

                // input half: A = h[l-1] (fresh)
                if (l > 0)
                    CHUNK2(hHiS + (uint32_t)((l - 1) * 9216), hLoS + (uint32_t)((l - 1) * 9216), 4);

                // write gate pre-activations, transposed: Gt[n'][m]
                #pragma unroll
                for (int mt = 0; mt < 2; mt++)
                    #pragma unroll
                    for (int nt = 0; nt < 8; nt++) {
                        int col = n0w + nt * 8 + 2 * tig;
                        int row = m0w + mt * 16 + gid;
                        GtS[col * 66 + row]           = acc[mt][nt][0];
                        GtS[(col + 1) * 66 + row]     = acc[mt][nt][1];
                        GtS[col * 66 + row + 8]       = acc[mt][nt][2];
                        GtS[(col + 1) * 66 + row + 8] = acc[mt][nt][3];
                    }
                BAR_ARRIVE(1, 512);         // Gt(l) ready -> EPI

                BAR_SYNC(3, 256);           // all MMA warps done reading W(l)
                if (!(t == T - 1 && l == 3)) stageW(wS, (l + 1) & 3, tid);
            }
        }
    } else {
        // ================= EPI group (warps 8-15) =================
        const int etid = tid - 256;
        const int b = etid & 63, jg = etid >> 6;

        BAR_ARRIVE(2, 512);                 // prime: "EPI(-1) done"
        for (int t = 0; t < T; t++) {
            for (int l = 0; l < 4; l++) {
                BAR_SYNC(1, 512);           // Gt(l) ready
                switch (l) {
                    case 0: EPI(0, cr0); break;
                    case 1: EPI(1, cr1); break;
                    case 2: EPI(2, cr2); break;
                    default: EPI(3, cr3); break;
                }
                if (l == 3) {
                    BAR_SYNC(4, 256);       // h3 visible across EPI warps
                    if (etid < 192) {
                        int jo = etid >> 6;
                        float a = boS[jo];
                        #pragma unroll 8
                        for (int j = 0; j < 64; j++)
                            a += woS[jo * 64 + j] *
                                 (__half2float(hHiE[(192 + b) * 72 + j]) +
                                  __half2float(hLoE[(192 + b) * 72 + j]));
                        out[(size_t)(bb0 + b) * (3 * T) + (size_t)t * 3 + jo] = a;
                        xS[jo * 64 + b] = a;
                    }
                }
                BAR_ARRIVE(2, 512);         // EPI(l) done
            }
        }
    }
}

// ---------------- entry ----------------
extern "C" void kernel_launch(void* const* d_in, const int* in_sizes, int n_in,
                              void* d_out, int out_size) {
    const float* conds     = (const float*)d_in[0];
    const float* W1        = (const float*)d_in[1];
    const float* b1        = (const float*)d_in[2];
    const float* W2        = (const float*)d_in[3];
    const float* b2        = (const float*)d_in[4];
    const float* W_ih0     = (const float*)d_in[5];
    const float* W_ih_rest = (const float*)d_in[6];
    const float* W_hh      = (const float*)d_in[7];
    const float* b_ih      = (const float*)d_in[8];
    const float* b_hh      = (const float*)d_in[9];
    const float* Wo        = (const float*)d_in[10];
    const float* bo        = (const float*)d_in[11];

    int B = in_sizes[0] / 8;
    if (B > B_MAX) B = B_MAX;
    int T = out_size / (B * 3);

    cudaFuncSetAttribute(lstm_main, cudaFuncAttributeMaxDynamicSharedMemorySize, SMEM_REQ);

    repack_k<<<(4 * 256 * 136 + 255) / 256, 256>>>(W_hh, W_ih_rest);
    embed_k<<<B, 128>>>(conds, W1, b1, W2, b2);
    lstm_main<<<B / 64, 512, SMEM_REQ>>>(b_ih, b_hh, W_ih0, Wo, bo, (float*)d_out, T);
}